// round 14
// baseline (speedup 1.0000x reference)
#include <cuda_runtime.h>
#include <cuda_fp16.h>
#include <cstdint>

#define T_TOK 4096
#define H_DIM 2048
#define I_DIM 4096
#define N_EXP 8
#define TOPK 2
#define N_SLOTS (T_TOK * TOPK)

#define BK 64                    // halves per k-tile
#define RSW 36                   // row stride in 32-bit words (144B)
#define TILE_B (128 * 144)       // 18432 bytes per 128 x 64h tile
#define ITILES 32                // I_DIM / 128
#define HTILES 16                // H_DIM / 128
#define KT_GU (H_DIM / BK)       // 32
#define KT_DN (I_DIM / BK)       // 64

#define GU_STAGES 4
#define GU_STAGE_B (3 * TILE_B)
#define GU_SMEM (GU_STAGES * GU_STAGE_B)   // 221184
#define DN_STAGES 4
#define DN_STAGE_B (2 * TILE_B)
#define DN_SMEM (DN_STAGES * DN_STAGE_B)   // 147456

#define NPERS 152
#define W_F4 16777216            // 8*4096*2048/4
#define H_F4 2097152             // 4096*2048/4
#define W2_CHUNKS 512            // w2 conversion chunks (32768 float4 each)

// ---------------- scratch (static device globals; no allocation) ------------
__device__ int    g_cnt[N_EXP];
__device__ int    g_cur[N_EXP];
__device__ int    g_off[N_EXP + 1];
__device__ int    g_tok_e[N_SLOTS];
__device__ float  g_tok_w[N_SLOTS];
__device__ int    g_tok_slot[N_SLOTS];
__device__ int    g_slot_tok[N_SLOTS];
__device__ int    g_qh, g_qd;
__device__ int    g_n_gu, g_n_dn;
__device__ int    g_items_gu[N_EXP * ITILES * 32 + W2_CHUNKS];
__device__ int    g_items_dn[N_EXP * HTILES * 32];
__device__ __half g_act_h[(size_t)N_SLOTS * I_DIM];       // 64MB
__device__ float  g_y[(size_t)N_SLOTS * H_DIM];           // 64MB slot-major down output
__device__ __half g_w1h[(size_t)N_EXP * I_DIM * H_DIM];   // 128MB
__device__ __half g_w3h[(size_t)N_EXP * I_DIM * H_DIM];   // 128MB
__device__ __half g_w2h[(size_t)N_EXP * H_DIM * I_DIM];   // 128MB
__device__ __half g_hidh[(size_t)T_TOK * H_DIM];          // 16MB

// ---------------- helpers ----------------------------------------------------
__device__ __forceinline__ uint32_t smem_u32(const void* p) {
    uint32_t a;
    asm("{ .reg .u64 t; cvta.to.shared.u64 t, %1; cvt.u32.u64 %0, t; }"
        : "=r"(a) : "l"(p));
    return a;
}
__device__ __forceinline__ void cpa16(uint32_t dst, const void* src) {
    asm volatile("cp.async.cg.shared.global [%0], [%1], 16;"
                 :: "r"(dst), "l"(src));
}
#define CP_COMMIT() asm volatile("cp.async.commit_group;" ::: "memory")
#define CP_WAIT3()  asm volatile("cp.async.wait_group 3;" ::: "memory")
#define CP_WAIT0()  asm volatile("cp.async.wait_group 0;" ::: "memory")

__device__ __forceinline__ void mma_f16(float c[4], const uint32_t a[4],
                                        const uint32_t b[2]) {
    asm("mma.sync.aligned.m16n8k16.row.col.f32.f16.f16.f32 "
        "{%0,%1,%2,%3}, {%4,%5,%6,%7}, {%8,%9}, {%0,%1,%2,%3};"
        : "+f"(c[0]), "+f"(c[1]), "+f"(c[2]), "+f"(c[3])
        : "r"(a[0]), "r"(a[1]), "r"(a[2]), "r"(a[3]),
          "r"(b[0]), "r"(b[1]));
}

// ---------------- routing / setup ---------------------------------------------
__global__ void reset_kernel() {
    int i = threadIdx.x;
    if (i < N_EXP) { g_cnt[i] = 0; g_cur[i] = 0; }
    if (i == 0)    { g_qh = 0; g_qd = 0; }
}

__device__ __forceinline__ void route_body(const float* __restrict__ logits, int t) {
    float v[N_EXP];
#pragma unroll
    for (int e = 0; e < N_EXP; e++) v[e] = logits[t * N_EXP + e];
    int e0 = 0; float b0 = v[0];
#pragma unroll
    for (int e = 1; e < N_EXP; e++) if (v[e] > b0) { b0 = v[e]; e0 = e; }
    int e1 = -1; float b1 = -3.0e38f;
#pragma unroll
    for (int e = 0; e < N_EXP; e++)
        if (e != e0 && v[e] > b1) { b1 = v[e]; e1 = e; }
    float w1v = __expf(b1 - b0);
    float inv = 1.0f / (1.0f + w1v);
    g_tok_e[2 * t]     = e0;
    g_tok_e[2 * t + 1] = e1;
    g_tok_w[2 * t]     = inv;
    g_tok_w[2 * t + 1] = w1v * inv;
    atomicAdd(&g_cnt[e0], 1);
    atomicAdd(&g_cnt[e1], 1);
}

// merged prepass (w1, w3, hidden -> fp16) + routing (first 16 blocks)
__global__ void prep_route(const float4* __restrict__ w1f,
                           const float4* __restrict__ w3f,
                           const float4* __restrict__ hidf,
                           const float* __restrict__ logits) {
    long long i = (long long)blockIdx.x * 256 + threadIdx.x;
    if (blockIdx.x < 16) route_body(logits, (int)i);

    const float4* s;
    __half2* d;
    if (i < W_F4)          { s = w1f + i;              d = (__half2*)g_w1h + 2 * i; }
    else if (i < 2 * W_F4) { long long k = i - W_F4;   s = w3f + k; d = (__half2*)g_w3h + 2 * k; }
    else                   { long long k = i - 2 * W_F4; s = hidf + k; d = (__half2*)g_hidh + 2 * k; }
    float4 v = *s;
    d[0] = __floats2half2_rn(v.x, v.y);
    d[1] = __floats2half2_rn(v.z, v.w);
}

// prefix scan + work-queue construction (1 block)
// W2C items are proportionally interleaved through the gateup queue so the
// 384MB of w2 conversion traffic hides under MMA-bound GEMM items instead of
// forming a DRAM-bound serial tail between the gateup and down phases.
__global__ void scan_build() {
    __shared__ int mtc[N_EXP], bgu[N_EXP + 1], bdn[N_EXP], s_N;
    int tid = threadIdx.x;
    if (tid == 0) {
        int acc = 0, tg = 0, td = 0;
        g_off[0] = 0;
        for (int e = 0; e < N_EXP; e++) {
            acc += g_cnt[e]; g_off[e + 1] = acc;
            int m = (g_cnt[e] + 127) >> 7;
            mtc[e] = m;
            bgu[e] = tg; tg += m * ITILES;
            bdn[e] = td; td += m * HTILES;
        }
        bgu[N_EXP] = tg;
        s_N = tg + W2_CHUNKS;
        g_n_gu = tg + W2_CHUNKS;
        g_n_dn = td;
    }
    __syncthreads();

    // gateup queue: proportional merge of GEMM items (expert-major, mt fastest)
    // with W2_CHUNKS conversion items.
    int N = s_N;
    for (int p = tid; p < N; p += 256) {
        int c_before = (int)(((long long)p * W2_CHUNKS) / N);
        int c_after  = (int)(((long long)(p + 1) * W2_CHUNKS) / N);
        int v;
        if (c_after > c_before) {
            v = (1 << 30) | c_before;            // w2 conversion chunk
        } else {
            int g = p - c_before;                 // gemm item index
            int e = 0;
#pragma unroll
            for (int q = 1; q < N_EXP; q++)
                if (g >= bgu[q]) e = q;
            int j = g - bgu[e];
            int m = mtc[e];
            int it = j / m, mt = j - it * m;      // mt fastest: L2 weight sharing
            v = (e << 11) | (it << 5) | mt;
        }
        g_items_gu[p] = v;
    }

    // down queue (unchanged)
    for (int e = 0; e < N_EXP; e++) {
        int m = mtc[e];
        int nd = m * HTILES;
        for (int j = tid; j < nd; j += 256) {
            int ht = j / m, mt = j - ht * m;
            g_items_dn[bdn[e] + j] = (e << 9) | (ht << 5) | mt;
        }
    }
}

__global__ void scatter_kernel() {
    int t = blockIdx.x * blockDim.x + threadIdx.x;
    if (t >= T_TOK) return;
#pragma unroll
    for (int k = 0; k < TOPK; k++) {
        int e = g_tok_e[2 * t + k];
        int p = atomicAdd(&g_cur[e], 1);
        int s = g_off[e] + p;
        g_slot_tok[s]         = t;
        g_tok_slot[2 * t + k] = s;
    }
}

// ---------------- phase B: act = silu(x @ w1^T) * (x @ w3^T) -----------------
__device__ __forceinline__ void gu_load(uint32_t sb, int e, int i0,
                                        const int* stok, int k0) {
    int tid = threadIdx.x;
    const __half* w1p = g_w1h + ((size_t)e * I_DIM + i0) * H_DIM + k0;
    const __half* w3p = g_w3h + ((size_t)e * I_DIM + i0) * H_DIM + k0;
#pragma unroll
    for (int j = 0; j < 4; j++) {
        int idx = tid + j * 256;
        int row = idx >> 3, sl = idx & 7;
        cpa16(sb + (uint32_t)(row * 144 + sl * 16),
              g_hidh + (size_t)stok[row] * H_DIM + k0 + sl * 8);
    }
#pragma unroll
    for (int j = 0; j < 4; j++) {
        int idx = tid + j * 256;
        int row = idx >> 3, sl = idx & 7;
        cpa16(sb + TILE_B + (uint32_t)(row * 144 + sl * 16),
              w1p + (size_t)row * H_DIM + sl * 8);
    }
#pragma unroll
    for (int j = 0; j < 4; j++) {
        int idx = tid + j * 256;
        int row = idx >> 3, sl = idx & 7;
        cpa16(sb + 2 * TILE_B + (uint32_t)(row * 144 + sl * 16),
              w3p + (size_t)row * H_DIM + sl * 8);
    }
}

__global__ __launch_bounds__(256, 1)
void gateup_h(const float4* __restrict__ w2f) {
    extern __shared__ uint32_t smw[];
    __shared__ int s_tok[128];
    __shared__ int s_item;

    int tid = threadIdx.x, lane = tid & 31, warp = tid >> 5;
    int warpM = warp & 1, warpN = warp >> 1;
    int r4 = lane >> 2, t4 = lane & 3;
    uint32_t sb0 = smem_u32(smw);
    int n_gu = g_n_gu;

    while (true) {
        __syncthreads();
        if (tid == 0) s_item = atomicAdd(&g_qh, 1);
        __syncthreads();
        int ii = s_item;
        if (ii >= n_gu) return;
        int item = g_items_gu[ii];

        if (item & (1 << 30)) {                 // w2 fp32->fp16 conversion chunk
            int chunk = item & 0x3FF;
            const float4* src = w2f + (size_t)chunk * 32768;
            __half2* dst = (__half2*)g_w2h + (size_t)chunk * 65536;
            for (int j = tid; j < 32768; j += 256) {
                float4 v = src[j];
                dst[2 * j]     = __floats2half2_rn(v.x, v.y);
                dst[2 * j + 1] = __floats2half2_rn(v.z, v.w);
            }
            continue;
        }

        int e  = item >> 11;
        int it = (item >> 5) & 63;
        int mt = item & 31;
        int slot0 = g_off[e] + mt * 128;
        int n_valid = min(128, g_off[e + 1] - slot0);
        int i0 = it * 128;

        for (int r = tid; r < 128; r += 256)
            s_tok[r] = (r < n_valid) ? g_slot_tok[slot0 + r] : g_slot_tok[slot0];
        __syncthreads();

#pragma unroll
        for (int s = 0; s < GU_STAGES - 1; s++) {
            gu_load(sb0 + s * GU_STAGE_B, e, i0, s_tok, s * BK);
            CP_COMMIT();
        }

        float accg[4][4][4] = {};
        float accu[4][4][4] = {};

        for (int kt = 0; kt < KT_GU; kt++) {
            int ldk = kt + GU_STAGES - 1;
            if (ldk < KT_GU)
                gu_load(sb0 + (ldk % GU_STAGES) * GU_STAGE_B, e, i0, s_tok, ldk * BK);
            CP_COMMIT();
            CP_WAIT3();
            __syncthreads();

            const uint32_t* As = smw + (size_t)(kt % GU_STAGES) * (GU_STAGE_B / 4);
            const uint32_t* Bg = As + TILE_B / 4;
            const uint32_t* Bu = As + 2 * (TILE_B / 4);

#pragma unroll
            for (int ks = 0; ks < 4; ks++) {
                int kw = ks * 8 + t4;
                uint32_t a[4][4];
#pragma unroll
                for (int m = 0; m < 4; m++) {
                    int rb = warpM * 64 + m * 16 + r4;
                    a[m][0] = As[rb * RSW + kw];
                    a[m][1] = As[(rb + 8) * RSW + kw];
                    a[m][2] = As[rb * RSW + kw + 4];
                    a[m][3] = As[(rb + 8) * RSW + kw + 4];
                }
#pragma unroll
                for (int nt = 0; nt < 4; nt++) {
                    int nb = warpN * 32 + nt * 8 + r4;
                    uint32_t bg[2] = { Bg[nb * RSW + kw], Bg[nb * RSW + kw + 4] };
                    uint32_t bu[2] = { Bu[nb * RSW + kw], Bu[nb * RSW + kw + 4] };
#pragma unroll
                    for (int m = 0; m < 4; m++) {
                        mma_f16(accg[m][nt], a[m], bg);
                        mma_f16(accu[m][nt], a[m], bu);
                    }
                }
            }
            __syncthreads();
        }
        CP_WAIT0();

        // epilogue: silu(gate)*up -> g_act_h
#pragma unroll
        for (int m = 0; m < 4; m++) {
#pragma unroll
            for (int nt = 0; nt < 4; nt++) {
                int r0 = warpM * 64 + m * 16 + r4;
                int c  = i0 + warpN * 32 + nt * 8 + t4 * 2;
                if (r0 < n_valid) {
                    float g0 = accg[m][nt][0], u0 = accu[m][nt][0];
                    float g1 = accg[m][nt][1], u1 = accu[m][nt][1];
                    *reinterpret_cast<__half2*>(g_act_h + (size_t)(slot0 + r0) * I_DIM + c) =
                        __floats2half2_rn((g0 / (1.0f + __expf(-g0))) * u0,
                                          (g1 / (1.0f + __expf(-g1))) * u1);
                }
                if (r0 + 8 < n_valid) {
                    float g2 = accg[m][nt][2], u2 = accu[m][nt][2];
                    float g3 = accg[m][nt][3], u3 = accu[m][nt][3];
                    *reinterpret_cast<__half2*>(g_act_h + (size_t)(slot0 + r0 + 8) * I_DIM + c) =
                        __floats2half2_rn((g2 / (1.0f + __expf(-g2))) * u2,
                                          (g3 / (1.0f + __expf(-g3))) * u3);
                }
            }
        }
    }
}

// ---------------- phase C: y[slot] = act @ w2^T (slot-major, unweighted) ------
__device__ __forceinline__ void dn_load(uint32_t sb, int e, int h0,
                                        int slot0, int k0) {
    int tid = threadIdx.x;
    const __half* w2p = g_w2h + ((size_t)e * H_DIM + h0) * I_DIM + k0;
#pragma unroll
    for (int j = 0; j < 4; j++) {
        int idx = tid + j * 256;
        int row = idx >> 3, sl = idx & 7;
        int sr = slot0 + row;
        if (sr >= N_SLOTS) sr = N_SLOTS - 1;
        cpa16(sb + (uint32_t)(row * 144 + sl * 16),
              g_act_h + (size_t)sr * I_DIM + k0 + sl * 8);
    }
#pragma unroll
    for (int j = 0; j < 4; j++) {
        int idx = tid + j * 256;
        int row = idx >> 3, sl = idx & 7;
        cpa16(sb + TILE_B + (uint32_t)(row * 144 + sl * 16),
              w2p + (size_t)row * I_DIM + sl * 8);
    }
}

__global__ __launch_bounds__(256, 1)
void down_h() {
    extern __shared__ uint32_t smw[];
    __shared__ int s_item;

    int tid = threadIdx.x, lane = tid & 31, warp = tid >> 5;
    int warpM = warp & 1, warpN = warp >> 1;
    int r4 = lane >> 2, t4 = lane & 3;
    uint32_t sb0 = smem_u32(smw);
    int n_dn = g_n_dn;

    while (true) {
        __syncthreads();
        if (tid == 0) s_item = atomicAdd(&g_qd, 1);
        __syncthreads();
        int ii = s_item;
        if (ii >= n_dn) return;
        int item = g_items_dn[ii];

        int e  = item >> 9;
        int ht = (item >> 5) & 15;
        int mt = item & 31;
        int slot0 = g_off[e] + mt * 128;
        int n_valid = min(128, g_off[e + 1] - slot0);
        int h0 = ht * 128;

#pragma unroll
        for (int s = 0; s < DN_STAGES - 1; s++) {
            dn_load(sb0 + s * DN_STAGE_B, e, h0, slot0, s * BK);
            CP_COMMIT();
        }

        float acc[4][4][4] = {};

        for (int kt = 0; kt < KT_DN; kt++) {
            int ldk = kt + DN_STAGES - 1;
            if (ldk < KT_DN)
                dn_load(sb0 + (ldk % DN_STAGES) * DN_STAGE_B, e, h0, slot0, ldk * BK);
            CP_COMMIT();
            CP_WAIT3();
            __syncthreads();

            const uint32_t* As = smw + (size_t)(kt % DN_STAGES) * (DN_STAGE_B / 4);
            const uint32_t* Bs = As + TILE_B / 4;

#pragma unroll
            for (int ks = 0; ks < 4; ks++) {
                int kw = ks * 8 + t4;
                uint32_t a[4][4];
#pragma unroll
                for (int m = 0; m < 4; m++) {
                    int rb = warpM * 64 + m * 16 + r4;
                    a[m][0] = As[rb * RSW + kw];
                    a[m][1] = As[(rb + 8) * RSW + kw];
                    a[m][2] = As[rb * RSW + kw + 4];
                    a[m][3] = As[(rb + 8) * RSW + kw + 4];
                }
#pragma unroll
                for (int nt = 0; nt < 4; nt++) {
                    int nb = warpN * 32 + nt * 8 + r4;
                    uint32_t b[2] = { Bs[nb * RSW + kw], Bs[nb * RSW + kw + 4] };
#pragma unroll
                    for (int m = 0; m < 4; m++) mma_f16(acc[m][nt], a[m], b);
                }
            }
            __syncthreads();
        }
        CP_WAIT0();

        // epilogue: plain stores into slot-major y
#pragma unroll
        for (int m = 0; m < 4; m++) {
#pragma unroll
            for (int nt = 0; nt < 4; nt++) {
                int r0 = warpM * 64 + m * 16 + r4;
                int c  = h0 + warpN * 32 + nt * 8 + t4 * 2;
                if (r0 < n_valid) {
                    float2 o = { acc[m][nt][0], acc[m][nt][1] };
                    *reinterpret_cast<float2*>(g_y + (size_t)(slot0 + r0) * H_DIM + c) = o;
                }
                if (r0 + 8 < n_valid) {
                    float2 o = { acc[m][nt][2], acc[m][nt][3] };
                    *reinterpret_cast<float2*>(g_y + (size_t)(slot0 + r0 + 8) * H_DIM + c) = o;
                }
            }
        }
    }
}

// ---------------- combine: out[t] = w0*y[s0] + w1*y[s1] ----------------------
__global__ void combine_kernel(float4* __restrict__ out) {
    int i = blockIdx.x * 256 + threadIdx.x;   // float4 index, 2M total
    int t = i >> 9;
    int c = i & 511;
    int s0 = g_tok_slot[2 * t], s1 = g_tok_slot[2 * t + 1];
    float w0 = g_tok_w[2 * t], w1 = g_tok_w[2 * t + 1];
    const float4* y = (const float4*)g_y;
    float4 a = y[(size_t)s0 * 512 + c];
    float4 b = y[(size_t)s1 * 512 + c];
    out[i] = make_float4(w0 * a.x + w1 * b.x, w0 * a.y + w1 * b.y,
                         w0 * a.z + w1 * b.z, w0 * a.w + w1 * b.w);
}

// ---------------- launch ------------------------------------------------------
extern "C" void kernel_launch(void* const* d_in, const int* in_sizes, int n_in,
                              void* d_out, int out_size) {
    const float* hidden = (const float*)d_in[0];
    const float* logits = (const float*)d_in[1];
    const float* w1     = (const float*)d_in[2];
    const float* w3     = (const float*)d_in[3];
    const float* w2     = (const float*)d_in[4];
    float* out = (float*)d_out;

    cudaFuncSetAttribute(gateup_h, cudaFuncAttributeMaxDynamicSharedMemorySize, GU_SMEM);
    cudaFuncSetAttribute(down_h,   cudaFuncAttributeMaxDynamicSharedMemorySize, DN_SMEM);

    reset_kernel<<<1, 32>>>();
    prep_route<<<(2 * W_F4 + H_F4) / 256, 256>>>((const float4*)w1, (const float4*)w3,
                                                 (const float4*)hidden, logits);
    scan_build<<<1, 256>>>();
    scatter_kernel<<<T_TOK / 256, 256>>>();

    gateup_h<<<NPERS, 256, GU_SMEM>>>((const float4*)w2);
    down_h<<<NPERS, 256, DN_SMEM>>>();
    combine_kernel<<<(T_TOK * H_DIM / 4) / 256, 256>>>((float4*)out);
}

// round 15
// speedup vs baseline: 1.0092x; 1.0092x over previous
#include <cuda_runtime.h>
#include <cuda_fp16.h>
#include <cstdint>

#define T_TOK 4096
#define H_DIM 2048
#define I_DIM 4096
#define N_EXP 8
#define TOPK 2
#define N_SLOTS (T_TOK * TOPK)

#define BK 64                    // halves per k-tile
#define RSW 36                   // row stride in 32-bit words (144B)
#define TILE_B (128 * 144)       // 18432 bytes per 128 x 64h tile
#define ITILES 32                // I_DIM / 128
#define HTILES 16                // H_DIM / 128
#define KT_GU (H_DIM / BK)       // 32
#define KT_DN (I_DIM / BK)       // 64

#define GU_STAGES 4
#define GU_STAGE_B (3 * TILE_B)
#define GU_SMEM (GU_STAGES * GU_STAGE_B)   // 221184
#define DN_STAGES 4
#define DN_STAGE_B (2 * TILE_B)
#define DN_SMEM (DN_STAGES * DN_STAGE_B)   // 147456

#define NPERS 152
#define W_F4 16777216            // 8*4096*2048/4
#define H_F4 2097152             // 4096*2048/4
#define W2_CHUNKS 512            // w2 conversion chunks (32768 float4 each)

// ---------------- scratch (static device globals; no allocation) ------------
__device__ int    g_cnt[N_EXP];
__device__ int    g_cur[N_EXP];
__device__ int    g_off[N_EXP + 1];
__device__ int    g_tok_e[N_SLOTS];
__device__ float  g_tok_w[N_SLOTS];
__device__ int    g_tok_slot[N_SLOTS];
__device__ int    g_slot_tok[N_SLOTS];
__device__ int    g_qh, g_qd;
__device__ int    g_n_gu, g_n_dn;
__device__ int    g_items_gu[N_EXP * ITILES * 32 + W2_CHUNKS];
__device__ int    g_items_dn[N_EXP * HTILES * 32];
__device__ __half g_act_h[(size_t)N_SLOTS * I_DIM];       // 64MB
__device__ float  g_y[(size_t)N_SLOTS * H_DIM];           // 64MB slot-major down output
__device__ __half g_w1h[(size_t)N_EXP * I_DIM * H_DIM];   // 128MB
__device__ __half g_w3h[(size_t)N_EXP * I_DIM * H_DIM];   // 128MB
__device__ __half g_w2h[(size_t)N_EXP * H_DIM * I_DIM];   // 128MB
__device__ __half g_hidh[(size_t)T_TOK * H_DIM];          // 16MB

// ---------------- helpers ----------------------------------------------------
__device__ __forceinline__ uint32_t smem_u32(const void* p) {
    uint32_t a;
    asm("{ .reg .u64 t; cvta.to.shared.u64 t, %1; cvt.u32.u64 %0, t; }"
        : "=r"(a) : "l"(p));
    return a;
}
__device__ __forceinline__ void cpa16(uint32_t dst, const void* src) {
    asm volatile("cp.async.cg.shared.global [%0], [%1], 16;"
                 :: "r"(dst), "l"(src));
}
#define CP_COMMIT() asm volatile("cp.async.commit_group;" ::: "memory")
#define CP_WAIT3()  asm volatile("cp.async.wait_group 3;" ::: "memory")
#define CP_WAIT0()  asm volatile("cp.async.wait_group 0;" ::: "memory")

__device__ __forceinline__ void mma_f16(float c[4], const uint32_t a[4],
                                        const uint32_t b[2]) {
    asm("mma.sync.aligned.m16n8k16.row.col.f32.f16.f16.f32 "
        "{%0,%1,%2,%3}, {%4,%5,%6,%7}, {%8,%9}, {%0,%1,%2,%3};"
        : "+f"(c[0]), "+f"(c[1]), "+f"(c[2]), "+f"(c[3])
        : "r"(a[0]), "r"(a[1]), "r"(a[2]), "r"(a[3]),
          "r"(b[0]), "r"(b[1]));
}

// ---------------- routing / setup ---------------------------------------------
__global__ void reset_kernel() {
    int i = threadIdx.x;
    if (i < N_EXP) { g_cnt[i] = 0; g_cur[i] = 0; }
    if (i == 0)    { g_qh = 0; g_qd = 0; }
}

__device__ __forceinline__ void route_body(const float* __restrict__ logits, int t) {
    float v[N_EXP];
#pragma unroll
    for (int e = 0; e < N_EXP; e++) v[e] = logits[t * N_EXP + e];
    int e0 = 0; float b0 = v[0];
#pragma unroll
    for (int e = 1; e < N_EXP; e++) if (v[e] > b0) { b0 = v[e]; e0 = e; }
    int e1 = -1; float b1 = -3.0e38f;
#pragma unroll
    for (int e = 0; e < N_EXP; e++)
        if (e != e0 && v[e] > b1) { b1 = v[e]; e1 = e; }
    float w1v = __expf(b1 - b0);
    float inv = 1.0f / (1.0f + w1v);
    g_tok_e[2 * t]     = e0;
    g_tok_e[2 * t + 1] = e1;
    g_tok_w[2 * t]     = inv;
    g_tok_w[2 * t + 1] = w1v * inv;
    atomicAdd(&g_cnt[e0], 1);
    atomicAdd(&g_cnt[e1], 1);
}

// merged prepass (w1, w3, hidden -> fp16) + routing (first 16 blocks)
__global__ void prep_route(const float4* __restrict__ w1f,
                           const float4* __restrict__ w3f,
                           const float4* __restrict__ hidf,
                           const float* __restrict__ logits) {
    long long i = (long long)blockIdx.x * 256 + threadIdx.x;
    if (blockIdx.x < 16) route_body(logits, (int)i);

    const float4* s;
    __half2* d;
    if (i < W_F4)          { s = w1f + i;              d = (__half2*)g_w1h + 2 * i; }
    else if (i < 2 * W_F4) { long long k = i - W_F4;   s = w3f + k; d = (__half2*)g_w3h + 2 * k; }
    else                   { long long k = i - 2 * W_F4; s = hidf + k; d = (__half2*)g_hidh + 2 * k; }
    float4 v = *s;
    d[0] = __floats2half2_rn(v.x, v.y);
    d[1] = __floats2half2_rn(v.z, v.w);
}

// prefix scan + work-queue construction (1 block)
__global__ void scan_build() {
    __shared__ int mtc[N_EXP], bgu[N_EXP], bdn[N_EXP], sgu;
    int tid = threadIdx.x;
    if (tid == 0) {
        int acc = 0, tg = 0, td = 0;
        g_off[0] = 0;
        for (int e = 0; e < N_EXP; e++) {
            acc += g_cnt[e]; g_off[e + 1] = acc;
            int m = (g_cnt[e] + 127) >> 7;
            mtc[e] = m;
            bgu[e] = tg; tg += m * ITILES;
            bdn[e] = td; td += m * HTILES;
        }
        sgu = tg;
        g_n_gu = tg + W2_CHUNKS;
        g_n_dn = td;
    }
    __syncthreads();
    for (int e = 0; e < N_EXP; e++) {
        int m = mtc[e];
        int n = m * ITILES;
        for (int j = tid; j < n; j += 256) {
            int it = j / m, mt = j - it * m;       // mt fastest: L2 weight-tile sharing
            g_items_gu[bgu[e] + j] = (e << 11) | (it << 5) | mt;
        }
        int nd = m * HTILES;
        for (int j = tid; j < nd; j += 256) {
            int ht = j / m, mt = j - ht * m;
            g_items_dn[bdn[e] + j] = (e << 9) | (ht << 5) | mt;
        }
    }
    __syncthreads();
    int base = sgu;
    for (int j = tid; j < W2_CHUNKS; j += 256)
        g_items_gu[base + j] = (1 << 30) | j;
}

__global__ void scatter_kernel() {
    int t = blockIdx.x * blockDim.x + threadIdx.x;
    if (t >= T_TOK) return;
#pragma unroll
    for (int k = 0; k < TOPK; k++) {
        int e = g_tok_e[2 * t + k];
        int p = atomicAdd(&g_cur[e], 1);
        int s = g_off[e] + p;
        g_slot_tok[s]         = t;
        g_tok_slot[2 * t + k] = s;
    }
}

// ---------------- phase B: act = silu(x @ w1^T) * (x @ w3^T) -----------------
__device__ __forceinline__ void gu_load(uint32_t sb, int e, int i0,
                                        const int* stok, int k0) {
    int tid = threadIdx.x;
    const __half* w1p = g_w1h + ((size_t)e * I_DIM + i0) * H_DIM + k0;
    const __half* w3p = g_w3h + ((size_t)e * I_DIM + i0) * H_DIM + k0;
#pragma unroll
    for (int j = 0; j < 4; j++) {
        int idx = tid + j * 256;
        int row = idx >> 3, sl = idx & 7;
        cpa16(sb + (uint32_t)(row * 144 + sl * 16),
              g_hidh + (size_t)stok[row] * H_DIM + k0 + sl * 8);
    }
#pragma unroll
    for (int j = 0; j < 4; j++) {
        int idx = tid + j * 256;
        int row = idx >> 3, sl = idx & 7;
        cpa16(sb + TILE_B + (uint32_t)(row * 144 + sl * 16),
              w1p + (size_t)row * H_DIM + sl * 8);
    }
#pragma unroll
    for (int j = 0; j < 4; j++) {
        int idx = tid + j * 256;
        int row = idx >> 3, sl = idx & 7;
        cpa16(sb + 2 * TILE_B + (uint32_t)(row * 144 + sl * 16),
              w3p + (size_t)row * H_DIM + sl * 8);
    }
}

__global__ __launch_bounds__(256, 1)
void gateup_h(const float4* __restrict__ w2f) {
    extern __shared__ uint32_t smw[];
    __shared__ int s_tok[128];
    __shared__ int s_item;

    int tid = threadIdx.x, lane = tid & 31, warp = tid >> 5;
    int warpM = warp & 1, warpN = warp >> 1;
    int r4 = lane >> 2, t4 = lane & 3;
    uint32_t sb0 = smem_u32(smw);
    int n_gu = g_n_gu;

    while (true) {
        __syncthreads();
        if (tid == 0) s_item = atomicAdd(&g_qh, 1);
        __syncthreads();
        int ii = s_item;
        if (ii >= n_gu) return;
        int item = g_items_gu[ii];

        if (item & (1 << 30)) {                 // w2 fp32->fp16 conversion chunk
            int chunk = item & 0x3FF;
            const float4* src = w2f + (size_t)chunk * 32768;
            __half2* dst = (__half2*)g_w2h + (size_t)chunk * 65536;
            for (int j = tid; j < 32768; j += 256) {
                float4 v = src[j];
                dst[2 * j]     = __floats2half2_rn(v.x, v.y);
                dst[2 * j + 1] = __floats2half2_rn(v.z, v.w);
            }
            continue;
        }

        int e  = item >> 11;
        int it = (item >> 5) & 63;
        int mt = item & 31;
        int slot0 = g_off[e] + mt * 128;
        int n_valid = min(128, g_off[e + 1] - slot0);
        int i0 = it * 128;

        for (int r = tid; r < 128; r += 256)
            s_tok[r] = (r < n_valid) ? g_slot_tok[slot0 + r] : g_slot_tok[slot0];
        __syncthreads();

#pragma unroll
        for (int s = 0; s < GU_STAGES - 1; s++) {
            gu_load(sb0 + s * GU_STAGE_B, e, i0, s_tok, s * BK);
            CP_COMMIT();
        }

        float accg[4][4][4] = {};
        float accu[4][4][4] = {};

        for (int kt = 0; kt < KT_GU; kt++) {
            int ldk = kt + GU_STAGES - 1;
            if (ldk < KT_GU)
                gu_load(sb0 + (ldk % GU_STAGES) * GU_STAGE_B, e, i0, s_tok, ldk * BK);
            CP_COMMIT();
            CP_WAIT3();
            __syncthreads();

            const uint32_t* As = smw + (size_t)(kt % GU_STAGES) * (GU_STAGE_B / 4);
            const uint32_t* Bg = As + TILE_B / 4;
            const uint32_t* Bu = As + 2 * (TILE_B / 4);

#pragma unroll
            for (int ks = 0; ks < 4; ks++) {
                int kw = ks * 8 + t4;
                uint32_t a[4][4];
#pragma unroll
                for (int m = 0; m < 4; m++) {
                    int rb = warpM * 64 + m * 16 + r4;
                    a[m][0] = As[rb * RSW + kw];
                    a[m][1] = As[(rb + 8) * RSW + kw];
                    a[m][2] = As[rb * RSW + kw + 4];
                    a[m][3] = As[(rb + 8) * RSW + kw + 4];
                }
#pragma unroll
                for (int nt = 0; nt < 4; nt++) {
                    int nb = warpN * 32 + nt * 8 + r4;
                    uint32_t bg[2] = { Bg[nb * RSW + kw], Bg[nb * RSW + kw + 4] };
                    uint32_t bu[2] = { Bu[nb * RSW + kw], Bu[nb * RSW + kw + 4] };
#pragma unroll
                    for (int m = 0; m < 4; m++) {
                        mma_f16(accg[m][nt], a[m], bg);
                        mma_f16(accu[m][nt], a[m], bu);
                    }
                }
            }
            __syncthreads();
        }
        CP_WAIT0();

        // epilogue: silu(gate)*up -> g_act_h
#pragma unroll
        for (int m = 0; m < 4; m++) {
#pragma unroll
            for (int nt = 0; nt < 4; nt++) {
                int r0 = warpM * 64 + m * 16 + r4;
                int c  = i0 + warpN * 32 + nt * 8 + t4 * 2;
                if (r0 < n_valid) {
                    float g0 = accg[m][nt][0], u0 = accu[m][nt][0];
                    float g1 = accg[m][nt][1], u1 = accu[m][nt][1];
                    *reinterpret_cast<__half2*>(g_act_h + (size_t)(slot0 + r0) * I_DIM + c) =
                        __floats2half2_rn((g0 / (1.0f + __expf(-g0))) * u0,
                                          (g1 / (1.0f + __expf(-g1))) * u1);
                }
                if (r0 + 8 < n_valid) {
                    float g2 = accg[m][nt][2], u2 = accu[m][nt][2];
                    float g3 = accg[m][nt][3], u3 = accu[m][nt][3];
                    *reinterpret_cast<__half2*>(g_act_h + (size_t)(slot0 + r0 + 8) * I_DIM + c) =
                        __floats2half2_rn((g2 / (1.0f + __expf(-g2))) * u2,
                                          (g3 / (1.0f + __expf(-g3))) * u3);
                }
            }
        }
    }
}

// ---------------- phase C: y[slot] = act @ w2^T (slot-major, unweighted) ------
__device__ __forceinline__ void dn_load(uint32_t sb, int e, int h0,
                                        int slot0, int k0) {
    int tid = threadIdx.x;
    const __half* w2p = g_w2h + ((size_t)e * H_DIM + h0) * I_DIM + k0;
#pragma unroll
    for (int j = 0; j < 4; j++) {
        int idx = tid + j * 256;
        int row = idx >> 3, sl = idx & 7;
        int sr = slot0 + row;
        if (sr >= N_SLOTS) sr = N_SLOTS - 1;
        cpa16(sb + (uint32_t)(row * 144 + sl * 16),
              g_act_h + (size_t)sr * I_DIM + k0 + sl * 8);
    }
#pragma unroll
    for (int j = 0; j < 4; j++) {
        int idx = tid + j * 256;
        int row = idx >> 3, sl = idx & 7;
        cpa16(sb + TILE_B + (uint32_t)(row * 144 + sl * 16),
              w2p + (size_t)row * I_DIM + sl * 8);
    }
}

__global__ __launch_bounds__(256, 1)
void down_h() {
    extern __shared__ uint32_t smw[];
    __shared__ int s_item;

    int tid = threadIdx.x, lane = tid & 31, warp = tid >> 5;
    int warpM = warp & 1, warpN = warp >> 1;
    int r4 = lane >> 2, t4 = lane & 3;
    uint32_t sb0 = smem_u32(smw);
    int n_dn = g_n_dn;

    while (true) {
        __syncthreads();
        if (tid == 0) s_item = atomicAdd(&g_qd, 1);
        __syncthreads();
        int ii = s_item;
        if (ii >= n_dn) return;
        int item = g_items_dn[ii];

        int e  = item >> 9;
        int ht = (item >> 5) & 15;
        int mt = item & 31;
        int slot0 = g_off[e] + mt * 128;
        int n_valid = min(128, g_off[e + 1] - slot0);
        int h0 = ht * 128;

#pragma unroll
        for (int s = 0; s < DN_STAGES - 1; s++) {
            dn_load(sb0 + s * DN_STAGE_B, e, h0, slot0, s * BK);
            CP_COMMIT();
        }

        float acc[4][4][4] = {};

        for (int kt = 0; kt < KT_DN; kt++) {
            int ldk = kt + DN_STAGES - 1;
            if (ldk < KT_DN)
                dn_load(sb0 + (ldk % DN_STAGES) * DN_STAGE_B, e, h0, slot0, ldk * BK);
            CP_COMMIT();
            CP_WAIT3();
            __syncthreads();

            const uint32_t* As = smw + (size_t)(kt % DN_STAGES) * (DN_STAGE_B / 4);
            const uint32_t* Bs = As + TILE_B / 4;

#pragma unroll
            for (int ks = 0; ks < 4; ks++) {
                int kw = ks * 8 + t4;
                uint32_t a[4][4];
#pragma unroll
                for (int m = 0; m < 4; m++) {
                    int rb = warpM * 64 + m * 16 + r4;
                    a[m][0] = As[rb * RSW + kw];
                    a[m][1] = As[(rb + 8) * RSW + kw];
                    a[m][2] = As[rb * RSW + kw + 4];
                    a[m][3] = As[(rb + 8) * RSW + kw + 4];
                }
#pragma unroll
                for (int nt = 0; nt < 4; nt++) {
                    int nb = warpN * 32 + nt * 8 + r4;
                    uint32_t b[2] = { Bs[nb * RSW + kw], Bs[nb * RSW + kw + 4] };
#pragma unroll
                    for (int m = 0; m < 4; m++) mma_f16(acc[m][nt], a[m], b);
                }
            }
            __syncthreads();
        }
        CP_WAIT0();

        // epilogue: plain stores into slot-major y
#pragma unroll
        for (int m = 0; m < 4; m++) {
#pragma unroll
            for (int nt = 0; nt < 4; nt++) {
                int r0 = warpM * 64 + m * 16 + r4;
                int c  = h0 + warpN * 32 + nt * 8 + t4 * 2;
                if (r0 < n_valid) {
                    float2 o = { acc[m][nt][0], acc[m][nt][1] };
                    *reinterpret_cast<float2*>(g_y + (size_t)(slot0 + r0) * H_DIM + c) = o;
                }
                if (r0 + 8 < n_valid) {
                    float2 o = { acc[m][nt][2], acc[m][nt][3] };
                    *reinterpret_cast<float2*>(g_y + (size_t)(slot0 + r0 + 8) * H_DIM + c) = o;
                }
            }
        }
    }
}

// ---------------- combine: out[t] = w0*y[s0] + w1*y[s1] ----------------------
__global__ void combine_kernel(float4* __restrict__ out) {
    int i = blockIdx.x * 256 + threadIdx.x;   // float4 index, 2M total
    int t = i >> 9;
    int c = i & 511;
    int s0 = g_tok_slot[2 * t], s1 = g_tok_slot[2 * t + 1];
    float w0 = g_tok_w[2 * t], w1 = g_tok_w[2 * t + 1];
    const float4* y = (const float4*)g_y;
    float4 a = y[(size_t)s0 * 512 + c];
    float4 b = y[(size_t)s1 * 512 + c];
    out[i] = make_float4(w0 * a.x + w1 * b.x, w0 * a.y + w1 * b.y,
                         w0 * a.z + w1 * b.z, w0 * a.w + w1 * b.w);
}

// ---------------- launch ------------------------------------------------------
extern "C" void kernel_launch(void* const* d_in, const int* in_sizes, int n_in,
                              void* d_out, int out_size) {
    const float* hidden = (const float*)d_in[0];
    const float* logits = (const float*)d_in[1];
    const float* w1     = (const float*)d_in[2];
    const float* w3     = (const float*)d_in[3];
    const float* w2     = (const float*)d_in[4];
    float* out = (float*)d_out;

    cudaFuncSetAttribute(gateup_h, cudaFuncAttributeMaxDynamicSharedMemorySize, GU_SMEM);
    cudaFuncSetAttribute(down_h,   cudaFuncAttributeMaxDynamicSharedMemorySize, DN_SMEM);

    reset_kernel<<<1, 32>>>();
    prep_route<<<(2 * W_F4 + H_F4) / 256, 256>>>((const float4*)w1, (const float4*)w3,
                                                 (const float4*)hidden, logits);
    scan_build<<<1, 256>>>();
    scatter_kernel<<<T_TOK / 256, 256>>>();

    gateup_h<<<NPERS, 256, GU_SMEM>>>((const float4*)w2);
    down_h<<<NPERS, 256, DN_SMEM>>>();
    combine_kernel<<<(T_TOK * H_DIM / 4) / 256, 256>>>((float4*)out);
}

// round 16
// speedup vs baseline: 1.0339x; 1.0245x over previous
#include <cuda_runtime.h>
#include <cuda_fp16.h>
#include <cstdint>

#define T_TOK 4096
#define H_DIM 2048
#define I_DIM 4096
#define N_EXP 8
#define TOPK 2
#define N_SLOTS (T_TOK * TOPK)

#define BK 128                   // halves per k-tile (doubled vs R5)
#define RSW 68                   // row stride in 32-bit words (272B; 68%32=4 -> conflict-free)
#define ROWB 272                 // row stride bytes
#define TILE_B (128 * ROWB)      // 34816 bytes per 128 x 128h tile
#define ITILES 32                // I_DIM / 128
#define HTILES 16                // H_DIM / 128
#define KT_GU (H_DIM / BK)       // 16
#define KT_DN (I_DIM / BK)       // 32

#define GU_STAGES 2
#define GU_STAGE_B (3 * TILE_B)              // 104448
#define GU_SMEM (GU_STAGES * GU_STAGE_B)     // 208896
#define DN_STAGES 3
#define DN_STAGE_B (2 * TILE_B)              // 69632
#define DN_SMEM (DN_STAGES * DN_STAGE_B)     // 208896

#define NPERS 152
#define W_F4 16777216            // 8*4096*2048/4
#define H_F4 2097152             // 4096*2048/4
#define W2_CHUNKS 512            // w2 conversion chunks (32768 float4 each)

// ---------------- scratch (static device globals; no allocation) ------------
__device__ int    g_cnt[N_EXP];
__device__ int    g_cur[N_EXP];
__device__ int    g_off[N_EXP + 1];
__device__ int    g_tok_e[N_SLOTS];
__device__ float  g_tok_w[N_SLOTS];
__device__ int    g_tok_slot[N_SLOTS];
__device__ int    g_slot_tok[N_SLOTS];
__device__ int    g_qh, g_qd;
__device__ int    g_n_gu, g_n_dn;
__device__ int    g_items_gu[N_EXP * ITILES * 32 + W2_CHUNKS];
__device__ int    g_items_dn[N_EXP * HTILES * 32];
__device__ __half g_act_h[(size_t)N_SLOTS * I_DIM];       // 64MB
__device__ float  g_y[(size_t)N_SLOTS * H_DIM];           // 64MB slot-major down output
__device__ __half g_w1h[(size_t)N_EXP * I_DIM * H_DIM];   // 128MB
__device__ __half g_w3h[(size_t)N_EXP * I_DIM * H_DIM];   // 128MB
__device__ __half g_w2h[(size_t)N_EXP * H_DIM * I_DIM];   // 128MB
__device__ __half g_hidh[(size_t)T_TOK * H_DIM];          // 16MB

// ---------------- helpers ----------------------------------------------------
__device__ __forceinline__ uint32_t smem_u32(const void* p) {
    uint32_t a;
    asm("{ .reg .u64 t; cvta.to.shared.u64 t, %1; cvt.u32.u64 %0, t; }"
        : "=r"(a) : "l"(p));
    return a;
}
__device__ __forceinline__ void cpa16(uint32_t dst, const void* src) {
    asm volatile("cp.async.cg.shared.global [%0], [%1], 16;"
                 :: "r"(dst), "l"(src));
}
#define CP_COMMIT() asm volatile("cp.async.commit_group;" ::: "memory")
#define CP_WAIT1()  asm volatile("cp.async.wait_group 1;" ::: "memory")
#define CP_WAIT2()  asm volatile("cp.async.wait_group 2;" ::: "memory")
#define CP_WAIT0()  asm volatile("cp.async.wait_group 0;" ::: "memory")

__device__ __forceinline__ void mma_f16(float c[4], const uint32_t a[4],
                                        const uint32_t b[2]) {
    asm("mma.sync.aligned.m16n8k16.row.col.f32.f16.f16.f32 "
        "{%0,%1,%2,%3}, {%4,%5,%6,%7}, {%8,%9}, {%0,%1,%2,%3};"
        : "+f"(c[0]), "+f"(c[1]), "+f"(c[2]), "+f"(c[3])
        : "r"(a[0]), "r"(a[1]), "r"(a[2]), "r"(a[3]),
          "r"(b[0]), "r"(b[1]));
}

// ---------------- routing / setup ---------------------------------------------
__global__ void reset_kernel() {
    int i = threadIdx.x;
    if (i < N_EXP) { g_cnt[i] = 0; g_cur[i] = 0; }
    if (i == 0)    { g_qh = 0; g_qd = 0; }
}

__device__ __forceinline__ void route_body(const float* __restrict__ logits, int t) {
    float v[N_EXP];
#pragma unroll
    for (int e = 0; e < N_EXP; e++) v[e] = logits[t * N_EXP + e];
    int e0 = 0; float b0 = v[0];
#pragma unroll
    for (int e = 1; e < N_EXP; e++) if (v[e] > b0) { b0 = v[e]; e0 = e; }
    int e1 = -1; float b1 = -3.0e38f;
#pragma unroll
    for (int e = 0; e < N_EXP; e++)
        if (e != e0 && v[e] > b1) { b1 = v[e]; e1 = e; }
    float w1v = __expf(b1 - b0);
    float inv = 1.0f / (1.0f + w1v);
    g_tok_e[2 * t]     = e0;
    g_tok_e[2 * t + 1] = e1;
    g_tok_w[2 * t]     = inv;
    g_tok_w[2 * t + 1] = w1v * inv;
    atomicAdd(&g_cnt[e0], 1);
    atomicAdd(&g_cnt[e1], 1);
}

// merged prepass (w1, w3, hidden -> fp16) + routing (first 16 blocks)
__global__ void prep_route(const float4* __restrict__ w1f,
                           const float4* __restrict__ w3f,
                           const float4* __restrict__ hidf,
                           const float* __restrict__ logits) {
    long long i = (long long)blockIdx.x * 256 + threadIdx.x;
    if (blockIdx.x < 16) route_body(logits, (int)i);

    const float4* s;
    __half2* d;
    if (i < W_F4)          { s = w1f + i;              d = (__half2*)g_w1h + 2 * i; }
    else if (i < 2 * W_F4) { long long k = i - W_F4;   s = w3f + k; d = (__half2*)g_w3h + 2 * k; }
    else                   { long long k = i - 2 * W_F4; s = hidf + k; d = (__half2*)g_hidh + 2 * k; }
    float4 v = *s;
    d[0] = __floats2half2_rn(v.x, v.y);
    d[1] = __floats2half2_rn(v.z, v.w);
}

// prefix scan + work-queue construction (1 block)
__global__ void scan_build() {
    __shared__ int mtc[N_EXP], bgu[N_EXP], bdn[N_EXP], sgu;
    int tid = threadIdx.x;
    if (tid == 0) {
        int acc = 0, tg = 0, td = 0;
        g_off[0] = 0;
        for (int e = 0; e < N_EXP; e++) {
            acc += g_cnt[e]; g_off[e + 1] = acc;
            int m = (g_cnt[e] + 127) >> 7;
            mtc[e] = m;
            bgu[e] = tg; tg += m * ITILES;
            bdn[e] = td; td += m * HTILES;
        }
        sgu = tg;
        g_n_gu = tg + W2_CHUNKS;
        g_n_dn = td;
    }
    __syncthreads();
    for (int e = 0; e < N_EXP; e++) {
        int m = mtc[e];
        int n = m * ITILES;
        for (int j = tid; j < n; j += 256) {
            int it = j / m, mt = j - it * m;       // mt fastest: L2 weight-tile sharing
            g_items_gu[bgu[e] + j] = (e << 11) | (it << 5) | mt;
        }
        int nd = m * HTILES;
        for (int j = tid; j < nd; j += 256) {
            int ht = j / m, mt = j - ht * m;
            g_items_dn[bdn[e] + j] = (e << 9) | (ht << 5) | mt;
        }
    }
    __syncthreads();
    int base = sgu;
    for (int j = tid; j < W2_CHUNKS; j += 256)
        g_items_gu[base + j] = (1 << 30) | j;
}

__global__ void scatter_kernel() {
    int t = blockIdx.x * blockDim.x + threadIdx.x;
    if (t >= T_TOK) return;
#pragma unroll
    for (int k = 0; k < TOPK; k++) {
        int e = g_tok_e[2 * t + k];
        int p = atomicAdd(&g_cur[e], 1);
        int s = g_off[e] + p;
        g_slot_tok[s]         = t;
        g_tok_slot[2 * t + k] = s;
    }
}

// ---------------- phase B: act = silu(x @ w1^T) * (x @ w3^T) -----------------
// per tile: 128 rows x 128 halves = 128 rows x 16 chunks of 16B = 2048 cp.async
__device__ __forceinline__ void gu_load(uint32_t sb, int e, int i0,
                                        const int* stok, int k0) {
    int tid = threadIdx.x;
    const __half* w1p = g_w1h + ((size_t)e * I_DIM + i0) * H_DIM + k0;
    const __half* w3p = g_w3h + ((size_t)e * I_DIM + i0) * H_DIM + k0;
#pragma unroll
    for (int j = 0; j < 8; j++) {
        int idx = tid + j * 256;
        int row = idx >> 4, sl = idx & 15;
        cpa16(sb + (uint32_t)(row * ROWB + sl * 16),
              g_hidh + (size_t)stok[row] * H_DIM + k0 + sl * 8);
    }
#pragma unroll
    for (int j = 0; j < 8; j++) {
        int idx = tid + j * 256;
        int row = idx >> 4, sl = idx & 15;
        cpa16(sb + TILE_B + (uint32_t)(row * ROWB + sl * 16),
              w1p + (size_t)row * H_DIM + sl * 8);
    }
#pragma unroll
    for (int j = 0; j < 8; j++) {
        int idx = tid + j * 256;
        int row = idx >> 4, sl = idx & 15;
        cpa16(sb + 2 * TILE_B + (uint32_t)(row * ROWB + sl * 16),
              w3p + (size_t)row * H_DIM + sl * 8);
    }
}

__global__ __launch_bounds__(256, 1)
void gateup_h(const float4* __restrict__ w2f) {
    extern __shared__ uint32_t smw[];
    __shared__ int s_tok[128];
    __shared__ int s_item;

    int tid = threadIdx.x, lane = tid & 31, warp = tid >> 5;
    int warpM = warp & 1, warpN = warp >> 1;
    int r4 = lane >> 2, t4 = lane & 3;
    uint32_t sb0 = smem_u32(smw);
    int n_gu = g_n_gu;

    while (true) {
        __syncthreads();
        if (tid == 0) s_item = atomicAdd(&g_qh, 1);
        __syncthreads();
        int ii = s_item;
        if (ii >= n_gu) return;
        int item = g_items_gu[ii];

        if (item & (1 << 30)) {                 // w2 fp32->fp16 conversion chunk
            int chunk = item & 0x3FF;
            const float4* src = w2f + (size_t)chunk * 32768;
            __half2* dst = (__half2*)g_w2h + (size_t)chunk * 65536;
            for (int j = tid; j < 32768; j += 256) {
                float4 v = src[j];
                dst[2 * j]     = __floats2half2_rn(v.x, v.y);
                dst[2 * j + 1] = __floats2half2_rn(v.z, v.w);
            }
            continue;
        }

        int e  = item >> 11;
        int it = (item >> 5) & 63;
        int mt = item & 31;
        int slot0 = g_off[e] + mt * 128;
        int n_valid = min(128, g_off[e + 1] - slot0);
        int i0 = it * 128;

        for (int r = tid; r < 128; r += 256)
            s_tok[r] = (r < n_valid) ? g_slot_tok[slot0 + r] : g_slot_tok[slot0];
        __syncthreads();

        // prologue: stage 0 in flight (GU_STAGES-1 = 1)
        gu_load(sb0, e, i0, s_tok, 0);
        CP_COMMIT();

        float accg[4][4][4] = {};
        float accu[4][4][4] = {};

        for (int kt = 0; kt < KT_GU; kt++) {
            int ldk = kt + GU_STAGES - 1;
            if (ldk < KT_GU)
                gu_load(sb0 + (ldk % GU_STAGES) * GU_STAGE_B, e, i0, s_tok, ldk * BK);
            CP_COMMIT();
            CP_WAIT1();
            __syncthreads();

            const uint32_t* As = smw + (size_t)(kt % GU_STAGES) * (GU_STAGE_B / 4);
            const uint32_t* Bg = As + TILE_B / 4;
            const uint32_t* Bu = As + 2 * (TILE_B / 4);

#pragma unroll
            for (int ks = 0; ks < 8; ks++) {      // 8 k16 steps per BK=128
                int kw = ks * 8 + t4;
                uint32_t a[4][4];
#pragma unroll
                for (int m = 0; m < 4; m++) {
                    int rb = warpM * 64 + m * 16 + r4;
                    a[m][0] = As[rb * RSW + kw];
                    a[m][1] = As[(rb + 8) * RSW + kw];
                    a[m][2] = As[rb * RSW + kw + 4];
                    a[m][3] = As[(rb + 8) * RSW + kw + 4];
                }
#pragma unroll
                for (int nt = 0; nt < 4; nt++) {
                    int nb = warpN * 32 + nt * 8 + r4;
                    uint32_t bg[2] = { Bg[nb * RSW + kw], Bg[nb * RSW + kw + 4] };
                    uint32_t bu[2] = { Bu[nb * RSW + kw], Bu[nb * RSW + kw + 4] };
#pragma unroll
                    for (int m = 0; m < 4; m++) {
                        mma_f16(accg[m][nt], a[m], bg);
                        mma_f16(accu[m][nt], a[m], bu);
                    }
                }
            }
            __syncthreads();
        }
        CP_WAIT0();

        // epilogue: silu(gate)*up -> g_act_h
#pragma unroll
        for (int m = 0; m < 4; m++) {
#pragma unroll
            for (int nt = 0; nt < 4; nt++) {
                int r0 = warpM * 64 + m * 16 + r4;
                int c  = i0 + warpN * 32 + nt * 8 + t4 * 2;
                if (r0 < n_valid) {
                    float g0 = accg[m][nt][0], u0 = accu[m][nt][0];
                    float g1 = accg[m][nt][1], u1 = accu[m][nt][1];
                    *reinterpret_cast<__half2*>(g_act_h + (size_t)(slot0 + r0) * I_DIM + c) =
                        __floats2half2_rn((g0 / (1.0f + __expf(-g0))) * u0,
                                          (g1 / (1.0f + __expf(-g1))) * u1);
                }
                if (r0 + 8 < n_valid) {
                    float g2 = accg[m][nt][2], u2 = accu[m][nt][2];
                    float g3 = accg[m][nt][3], u3 = accu[m][nt][3];
                    *reinterpret_cast<__half2*>(g_act_h + (size_t)(slot0 + r0 + 8) * I_DIM + c) =
                        __floats2half2_rn((g2 / (1.0f + __expf(-g2))) * u2,
                                          (g3 / (1.0f + __expf(-g3))) * u3);
                }
            }
        }
    }
}

// ---------------- phase C: y[slot] = act @ w2^T (slot-major, unweighted) ------
__device__ __forceinline__ void dn_load(uint32_t sb, int e, int h0,
                                        int slot0, int k0) {
    int tid = threadIdx.x;
    const __half* w2p = g_w2h + ((size_t)e * H_DIM + h0) * I_DIM + k0;
#pragma unroll
    for (int j = 0; j < 8; j++) {
        int idx = tid + j * 256;
        int row = idx >> 4, sl = idx & 15;
        int sr = slot0 + row;
        if (sr >= N_SLOTS) sr = N_SLOTS - 1;
        cpa16(sb + (uint32_t)(row * ROWB + sl * 16),
              g_act_h + (size_t)sr * I_DIM + k0 + sl * 8);
    }
#pragma unroll
    for (int j = 0; j < 8; j++) {
        int idx = tid + j * 256;
        int row = idx >> 4, sl = idx & 15;
        cpa16(sb + TILE_B + (uint32_t)(row * ROWB + sl * 16),
              w2p + (size_t)row * I_DIM + sl * 8);
    }
}

__global__ __launch_bounds__(256, 1)
void down_h() {
    extern __shared__ uint32_t smw[];
    __shared__ int s_item;

    int tid = threadIdx.x, lane = tid & 31, warp = tid >> 5;
    int warpM = warp & 1, warpN = warp >> 1;
    int r4 = lane >> 2, t4 = lane & 3;
    uint32_t sb0 = smem_u32(smw);
    int n_dn = g_n_dn;

    while (true) {
        __syncthreads();
        if (tid == 0) s_item = atomicAdd(&g_qd, 1);
        __syncthreads();
        int ii = s_item;
        if (ii >= n_dn) return;
        int item = g_items_dn[ii];

        int e  = item >> 9;
        int ht = (item >> 5) & 15;
        int mt = item & 31;
        int slot0 = g_off[e] + mt * 128;
        int n_valid = min(128, g_off[e + 1] - slot0);
        int h0 = ht * 128;

#pragma unroll
        for (int s = 0; s < DN_STAGES - 1; s++) {
            dn_load(sb0 + s * DN_STAGE_B, e, h0, slot0, s * BK);
            CP_COMMIT();
        }

        float acc[4][4][4] = {};

        for (int kt = 0; kt < KT_DN; kt++) {
            int ldk = kt + DN_STAGES - 1;
            if (ldk < KT_DN)
                dn_load(sb0 + (ldk % DN_STAGES) * DN_STAGE_B, e, h0, slot0, ldk * BK);
            CP_COMMIT();
            CP_WAIT2();
            __syncthreads();

            const uint32_t* As = smw + (size_t)(kt % DN_STAGES) * (DN_STAGE_B / 4);
            const uint32_t* Bs = As + TILE_B / 4;

#pragma unroll
            for (int ks = 0; ks < 8; ks++) {
                int kw = ks * 8 + t4;
                uint32_t a[4][4];
#pragma unroll
                for (int m = 0; m < 4; m++) {
                    int rb = warpM * 64 + m * 16 + r4;
                    a[m][0] = As[rb * RSW + kw];
                    a[m][1] = As[(rb + 8) * RSW + kw];
                    a[m][2] = As[rb * RSW + kw + 4];
                    a[m][3] = As[(rb + 8) * RSW + kw + 4];
                }
#pragma unroll
                for (int nt = 0; nt < 4; nt++) {
                    int nb = warpN * 32 + nt * 8 + r4;
                    uint32_t b[2] = { Bs[nb * RSW + kw], Bs[nb * RSW + kw + 4] };
#pragma unroll
                    for (int m = 0; m < 4; m++) mma_f16(acc[m][nt], a[m], b);
                }
            }
            __syncthreads();
        }
        CP_WAIT0();

        // epilogue: plain stores into slot-major y
#pragma unroll
        for (int m = 0; m < 4; m++) {
#pragma unroll
            for (int nt = 0; nt < 4; nt++) {
                int r0 = warpM * 64 + m * 16 + r4;
                int c  = h0 + warpN * 32 + nt * 8 + t4 * 2;
                if (r0 < n_valid) {
                    float2 o = { acc[m][nt][0], acc[m][nt][1] };
                    *reinterpret_cast<float2*>(g_y + (size_t)(slot0 + r0) * H_DIM + c) = o;
                }
                if (r0 + 8 < n_valid) {
                    float2 o = { acc[m][nt][2], acc[m][nt][3] };
                    *reinterpret_cast<float2*>(g_y + (size_t)(slot0 + r0 + 8) * H_DIM + c) = o;
                }
            }
        }
    }
}

// ---------------- combine: out[t] = w0*y[s0] + w1*y[s1] ----------------------
__global__ void combine_kernel(float4* __restrict__ out) {
    int i = blockIdx.x * 256 + threadIdx.x;   // float4 index, 2M total
    int t = i >> 9;
    int c = i & 511;
    int s0 = g_tok_slot[2 * t], s1 = g_tok_slot[2 * t + 1];
    float w0 = g_tok_w[2 * t], w1 = g_tok_w[2 * t + 1];
    const float4* y = (const float4*)g_y;
    float4 a = y[(size_t)s0 * 512 + c];
    float4 b = y[(size_t)s1 * 512 + c];
    out[i] = make_float4(w0 * a.x + w1 * b.x, w0 * a.y + w1 * b.y,
                         w0 * a.z + w1 * b.z, w0 * a.w + w1 * b.w);
}

// ---------------- launch ------------------------------------------------------
extern "C" void kernel_launch(void* const* d_in, const int* in_sizes, int n_in,
                              void* d_out, int out_size) {
    const float* hidden = (const float*)d_in[0];
    const float* logits = (const float*)d_in[1];
    const float* w1     = (const float*)d_in[2];
    const float* w3     = (const float*)d_in[3];
    const float* w2     = (const float*)d_in[4];
    float* out = (float*)d_out;

    cudaFuncSetAttribute(gateup_h, cudaFuncAttributeMaxDynamicSharedMemorySize, GU_SMEM);
    cudaFuncSetAttribute(down_h,   cudaFuncAttributeMaxDynamicSharedMemorySize, DN_SMEM);

    reset_kernel<<<1, 32>>>();
    prep_route<<<(2 * W_F4 + H_F4) / 256, 256>>>((const float4*)w1, (const float4*)w3,
                                                 (const float4*)hidden, logits);
    scan_build<<<1, 256>>>();
    scatter_kernel<<<T_TOK / 256, 256>>>();

    gateup_h<<<NPERS, 256, GU_SMEM>>>((const float4*)w2);
    down_h<<<NPERS, 256, DN_SMEM>>>();
    combine_kernel<<<(T_TOK * H_DIM / 4) / 256, 256>>>((float4*)out);
}